// round 14
// baseline (speedup 1.0000x reference)
#include <cuda_runtime.h>
#include <math.h>

// Problem constants (fixed shapes)
#define B_    16
#define H_    16
#define BH    256          // B*H
#define L_    4
#define D_    2048
#define HD_   128
#define KV_   4096
#define KVT   4100         // KV + L
#define M_    64           // B*L rows
#define CH2   512          // kv chunk size (8 chunks cover KV exactly)
#define NCHK  8
#define SPLITK 4
#define CHP   (CH2 + 4)    // padded chunk rows (tail lives in chunk 7)

// Output layout (concatenated): out[131072], keys[256*4100*128], values[...]
#define OUT_ELEMS   (M_*D_)                 // 131072
#define KEYS_ELEMS  (BH*KVT*HD_)            // 134348800

// Scratch
__device__ float g_qkv[3*M_*D_];            // raw q,k,v projections
__device__ float g_q[BH*L_*HD_];            // roped q, (b,h,l,hd)
__device__ float g_attnout[BH*L_*HD_];      // attention output (b,h,l,hd)
__device__ float g_pout[BH*L_*NCHK*HD_];    // per-chunk unnormalized partials
__device__ float g_cm[BH*L_*NCHK];          // per-chunk max
__device__ float g_cs[BH*L_*NCHK];          // per-chunk sum(exp(.-max))
__device__ float g_rc[L_][64];
__device__ float g_rs[L_][64];

// ---------------------------------------------------------------------------
// init: zero split-K accumulators + out region, build rope table (fp64 trig)
// ---------------------------------------------------------------------------
__global__ void __launch_bounds__(256) init_kernel(float* __restrict__ out) {
    int t = blockIdx.x * blockDim.x + threadIdx.x;
    if (t < 3*M_*D_) g_qkv[t] = 0.f;
    if (t < OUT_ELEMS) out[t] = 0.f;
    if (t < 256) {
        int l = t >> 6, i = t & 63;
        double inv = pow(10000.0, -(double)(2*i) / 128.0);
        float invf = (float)inv;                       // match jax f32 inv_freq
        float ang = (float)(KV_ + l) * invf;           // f32 angle like reference
        g_rc[l][i] = (float)cos((double)ang);
        g_rs[l][i] = (float)sin((double)ang);
    }
}

// ---------------------------------------------------------------------------
// Fused QKV projection: C[64 x 2048] += A[64 x 2048] * W[2048 x 2048]^T
// ---------------------------------------------------------------------------
__global__ void __launch_bounds__(256) gemm_qkv(const float* __restrict__ A,
                         const float* __restrict__ qw,
                         const float* __restrict__ kw,
                         const float* __restrict__ vw) {
    __shared__ float As[32][64];
    __shared__ float Bs[32][64];
    int mode = blockIdx.z;
    const float* __restrict__ W = (mode == 0) ? qw : ((mode == 1) ? kw : vw);
    float* __restrict__ C = g_qkv + mode * M_ * D_;

    int tid = threadIdx.x;
    int tx = tid & 15, ty = tid >> 4;
    int n0 = blockIdx.x * 64;
    int KS = D_ / gridDim.y;
    int kbase = blockIdx.y * KS;

    float acc[4][4] = {};

    for (int k0 = kbase; k0 < kbase + KS; k0 += 32) {
        #pragma unroll
        for (int rep = 0; rep < 2; rep++) {
            int fid = tid + rep * 256;
            int row = fid >> 3;
            int c4  = (fid & 7) * 4;
            int k   = k0 + c4;
            float4 av = *(const float4*)(A + row * D_ + k);
            float4 bv = *(const float4*)(W + (n0 + row) * D_ + k);
            As[c4+0][row] = av.x; As[c4+1][row] = av.y;
            As[c4+2][row] = av.z; As[c4+3][row] = av.w;
            Bs[c4+0][row] = bv.x; Bs[c4+1][row] = bv.y;
            Bs[c4+2][row] = bv.z; Bs[c4+3][row] = bv.w;
        }
        __syncthreads();
        #pragma unroll
        for (int kk = 0; kk < 32; kk++) {
            float a[4], b[4];
            #pragma unroll
            for (int i = 0; i < 4; i++) a[i] = As[kk][ty*4 + i];
            #pragma unroll
            for (int j = 0; j < 4; j++) b[j] = Bs[kk][tx*4 + j];
            #pragma unroll
            for (int i = 0; i < 4; i++)
                #pragma unroll
                for (int j = 0; j < 4; j++)
                    acc[i][j] += a[i] * b[j];
        }
        __syncthreads();
    }

    #pragma unroll
    for (int i = 0; i < 4; i++)
        #pragma unroll
        for (int j = 0; j < 4; j++)
            atomicAdd(&C[(ty*4 + i) * D_ + n0 + tx*4 + j], acc[i][j]);
}

// ---------------------------------------------------------------------------
// O projection: out[64 x 2048] += attnout(gathered) * OW^T, split-K atomic
// ---------------------------------------------------------------------------
__global__ void __launch_bounds__(256) gemm_o(const float* __restrict__ W,
                                              float* __restrict__ C) {
    __shared__ float As[32][64];
    __shared__ float Bs[32][64];
    const float* __restrict__ A = g_attnout;

    int tid = threadIdx.x;
    int tx = tid & 15, ty = tid >> 4;
    int n0 = blockIdx.x * 64;
    int KS = D_ / gridDim.y;
    int kbase = blockIdx.y * KS;

    float acc[4][4] = {};

    for (int k0 = kbase; k0 < kbase + KS; k0 += 32) {
        #pragma unroll
        for (int rep = 0; rep < 2; rep++) {
            int fid = tid + rep * 256;
            int row = fid >> 3;
            int c4  = (fid & 7) * 4;
            int k   = k0 + c4;
            int b = row >> 2, l = row & 3, h = k >> 7, hd = k & 127;
            float4 av = *(const float4*)(A + (((b << 4) + h) * 4 + l) * HD_ + hd);
            float4 bv = *(const float4*)(W + (n0 + row) * D_ + k);
            As[c4+0][row] = av.x; As[c4+1][row] = av.y;
            As[c4+2][row] = av.z; As[c4+3][row] = av.w;
            Bs[c4+0][row] = bv.x; Bs[c4+1][row] = bv.y;
            Bs[c4+2][row] = bv.z; Bs[c4+3][row] = bv.w;
        }
        __syncthreads();
        #pragma unroll
        for (int kk = 0; kk < 32; kk++) {
            float a[4], b[4];
            #pragma unroll
            for (int i = 0; i < 4; i++) a[i] = As[kk][ty*4 + i];
            #pragma unroll
            for (int j = 0; j < 4; j++) b[j] = Bs[kk][tx*4 + j];
            #pragma unroll
            for (int i = 0; i < 4; i++)
                #pragma unroll
                for (int j = 0; j < 4; j++)
                    acc[i][j] += a[i] * b[j];
        }
        __syncthreads();
    }

    #pragma unroll
    for (int i = 0; i < 4; i++)
        #pragma unroll
        for (int j = 0; j < 4; j++)
            atomicAdd(&C[(ty*4 + i) * D_ + n0 + tx*4 + j], acc[i][j]);
}

// ---------------------------------------------------------------------------
// rope + scatter: q -> g_q (roped), k -> keys tail (roped), v -> values tail
// ---------------------------------------------------------------------------
__global__ void __launch_bounds__(256) rope_scatter(float* __restrict__ keys,
                                                    float* __restrict__ values) {
    int mat = blockIdx.y;                       // 0=q, 1=k, 2=v
    int p = blockIdx.x * 256 + threadIdx.x;     // pair id, 0..65535
    int m  = p >> 10;                            // row 0..63
    int n0 = (p & 1023) * 2;                     // even column
    int b = m >> 2, l = m & 3;
    int h = n0 >> 7, hd = n0 & 127;
    const float* src = g_qkv + mat * M_ * D_ + m * D_ + n0;
    float x1 = src[0], x2 = src[1];
    int bh = (b << 4) + h;
    if (mat == 2) {
        float* dst = values + (bh * KVT + KV_ + l) * HD_ + hd;
        dst[0] = x1; dst[1] = x2;
    } else {
        int i = hd >> 1;
        float c = g_rc[l][i], s = g_rs[l][i];
        float r1 = x1 * c - x2 * s;
        float r2 = x1 * s + x2 * c;
        if (mat == 0) {
            float* dst = g_q + (bh * 4 + l) * HD_ + hd;
            dst[0] = r1; dst[1] = r2;
        } else {
            float* dst = keys + (bh * KVT + KV_ + l) * HD_ + hd;
            dst[0] = r1; dst[1] = r2;
        }
    }
}

// ---------------------------------------------------------------------------
// helpers for the streaming kernel
// ---------------------------------------------------------------------------
__device__ __forceinline__ void dot4(float4 kv, float4 q0, float4 q1,
                                     float4 q2, float4 q3,
                                     float& s0, float& s1, float& s2, float& s3) {
    s0 = kv.x*q0.x + kv.y*q0.y + kv.z*q0.z + kv.w*q0.w;
    s1 = kv.x*q1.x + kv.y*q1.y + kv.z*q1.z + kv.w*q1.w;
    s2 = kv.x*q2.x + kv.y*q2.y + kv.z*q2.z + kv.w*q2.w;
    s3 = kv.x*q3.x + kv.y*q3.y + kv.z*q3.z + kv.w*q3.w;
}

__device__ __forceinline__ void red4(float& s0, float& s1, float& s2, float& s3) {
    #pragma unroll
    for (int off = 16; off; off >>= 1) {
        s0 += __shfl_xor_sync(0xFFFFFFFFu, s0, off);
        s1 += __shfl_xor_sync(0xFFFFFFFFu, s1, off);
        s2 += __shfl_xor_sync(0xFFFFFFFFu, s2, off);
        s3 += __shfl_xor_sync(0xFFFFFFFFu, s3, off);
    }
}

__device__ __forceinline__ float4 ldcs4(const float* p) {
    return __ldcs((const float4*)p);
}
__device__ __forceinline__ void stcs4(float* p, float4 v) {
    __stcs((float4*)p, v);
}

// ---------------------------------------------------------------------------
// Merged flash-style streaming kernel, one CTA per (bh, chunk):
//   phase A: stream K chunk -> keys, scores into smem, chunk (max, sum)
//   phase B: stream V chunk -> values, accumulate V weighted by exp(s-max)
//   writes unnormalized partial out + (max, sum); exact combine comes later.
// Scores never touch global memory.
// ---------------------------------------------------------------------------
__global__ void __launch_bounds__(256) attn_stream(
        const float* __restrict__ kc, const float* __restrict__ vc,
        const float* __restrict__ mask,
        float* __restrict__ keys, float* __restrict__ values) {
    // shared layout: ssc[4][CHP] | sp[CHP][4] | redbuf[4][8]
    __shared__ __align__(16) float smem_all[4*CHP + CHP*4 + 32];
    float* ssc    = smem_all;                 // [qi][i] : ssc[qi*CHP + i]
    float* sp     = smem_all + 4*CHP;         // [i][qi] : sp[i*4 + qi]
    float* redbuf = smem_all + 8*CHP;         // [qi][warp]

    int bh = blockIdx.x;
    int cy = blockIdx.y;
    int start = cy * CH2;
    bool last = (cy == 7);
    int tid = threadIdx.x, w = tid >> 5, lane = tid & 31;

    const float* qb = g_q + bh * 4 * HD_ + lane * 4;
    float4 q0 = *(const float4*)(qb + 0 * HD_);
    float4 q1 = *(const float4*)(qb + 1 * HD_);
    float4 q2 = *(const float4*)(qb + 2 * HD_);
    float4 q3 = *(const float4*)(qb + 3 * HD_);

    // ---- phase A: K stream + raw scores ----
    {
        const float* kin  = kc   + (bh * KV_ + start) * HD_ + lane * 4;
        float*       kout = keys + (bh * KVT + start) * HD_ + lane * 4;
        for (int rr = w; rr < CH2; rr += 16) {
            float4 ka = ldcs4(kin + rr * HD_);
            float4 kb = ldcs4(kin + (rr + 8) * HD_);
            stcs4(kout + rr * HD_, ka);
            stcs4(kout + (rr + 8) * HD_, kb);
            float a0, a1, a2, a3, b0, b1, b2, b3;
            dot4(ka, q0, q1, q2, q3, a0, a1, a2, a3);
            dot4(kb, q0, q1, q2, q3, b0, b1, b2, b3);
            red4(a0, a1, a2, a3);
            red4(b0, b1, b2, b3);
            if (lane == 0) {
                ssc[0*CHP + rr] = a0; ssc[1*CHP + rr] = a1;
                ssc[2*CHP + rr] = a2; ssc[3*CHP + rr] = a3;
                ssc[0*CHP + rr+8] = b0; ssc[1*CHP + rr+8] = b1;
                ssc[2*CHP + rr+8] = b2; ssc[3*CHP + rr+8] = b3;
            }
        }
        if (last && w < 4) {                     // tail rows 4096..4099 (in keys)
            int r = KV_ + w;
            float4 kv = *(const float4*)(keys + (bh * KVT + r) * HD_ + lane * 4);
            float t0, t1, t2, t3;
            dot4(kv, q0, q1, q2, q3, t0, t1, t2, t3);
            red4(t0, t1, t2, t3);
            if (lane == 0) {
                ssc[0*CHP + CH2 + w] = t0; ssc[1*CHP + CH2 + w] = t1;
                ssc[2*CHP + CH2 + w] = t2; ssc[3*CHP + CH2 + w] = t3;
            }
        }
    }
    __syncthreads();

    const float scale = 0.08838834764831845f;   // 128^-0.5
    int len = last ? CHP : CH2;

    // ---- scale + mask in smem, per-thread max ----
    float tmax[4] = {-3.0e38f, -3.0e38f, -3.0e38f, -3.0e38f};
    #pragma unroll
    for (int qi = 0; qi < 4; qi++) {
        for (int i = tid; i < len; i += 256) {
            float val = ssc[qi*CHP + i] * scale + mask[qi * KVT + start + i];
            ssc[qi*CHP + i] = val;
            tmax[qi] = fmaxf(tmax[qi], val);
        }
    }
    #pragma unroll
    for (int off = 16; off; off >>= 1) {
        #pragma unroll
        for (int qi = 0; qi < 4; qi++)
            tmax[qi] = fmaxf(tmax[qi], __shfl_xor_sync(0xFFFFFFFFu, tmax[qi], off));
    }
    if (lane == 0) {
        #pragma unroll
        for (int qi = 0; qi < 4; qi++) redbuf[qi*8 + w] = tmax[qi];
    }
    __syncthreads();
    float bm[4];
    #pragma unroll
    for (int qi = 0; qi < 4; qi++) {
        float m = redbuf[qi*8];
        #pragma unroll
        for (int j = 1; j < 8; j++) m = fmaxf(m, redbuf[qi*8 + j]);
        bm[qi] = m;
    }
    __syncthreads();                             // all reads of redbuf done

    // ---- exp into sp (transposed), per-thread sum ----
    float tsum[4] = {0.f, 0.f, 0.f, 0.f};
    #pragma unroll
    for (int qi = 0; qi < 4; qi++) {
        for (int i = tid; i < len; i += 256) {
            float e = expf(ssc[qi*CHP + i] - bm[qi]);
            sp[i*4 + qi] = e;
            tsum[qi] += e;
        }
    }
    if (!last) {                                 // pad unused tail rows with 0
        for (int i = CH2 + tid; i < CHP; i += 256) {
            sp[i*4+0] = 0.f; sp[i*4+1] = 0.f; sp[i*4+2] = 0.f; sp[i*4+3] = 0.f;
        }
    }
    red4(tsum[0], tsum[1], tsum[2], tsum[3]);
    if (lane == 0) {
        #pragma unroll
        for (int qi = 0; qi < 4; qi++) redbuf[qi*8 + w] = tsum[qi];
    }
    __syncthreads();
    if (tid < 4) {
        float s = 0.f;
        #pragma unroll
        for (int j = 0; j < 8; j++) s += redbuf[tid*8 + j];
        g_cm[(bh * 4 + tid) * NCHK + cy] = bm[tid];
        g_cs[(bh * 4 + tid) * NCHK + cy] = s;
    }
    __syncthreads();

    // ---- phase B: V stream + weighted accumulation ----
    float a0[4] = {}, a1[4] = {}, a2[4] = {}, a3[4] = {};
    {
        const float* vin  = vc     + (bh * KV_ + start) * HD_ + lane * 4;
        float*       vout = values + (bh * KVT + start) * HD_ + lane * 4;
        for (int rr = w; rr < CH2; rr += 16) {
            float4 va = ldcs4(vin + rr * HD_);
            float4 vb = ldcs4(vin + (rr + 8) * HD_);
            stcs4(vout + rr * HD_, va);
            stcs4(vout + (rr + 8) * HD_, vb);
            float4 pa = *(const float4*)(sp + rr * 4);
            float4 pb = *(const float4*)(sp + (rr + 8) * 4);
            a0[0] += pa.x*va.x; a0[1] += pa.x*va.y; a0[2] += pa.x*va.z; a0[3] += pa.x*va.w;
            a1[0] += pa.y*va.x; a1[1] += pa.y*va.y; a1[2] += pa.y*va.z; a1[3] += pa.y*va.w;
            a2[0] += pa.z*va.x; a2[1] += pa.z*va.y; a2[2] += pa.z*va.z; a2[3] += pa.z*va.w;
            a3[0] += pa.w*va.x; a3[1] += pa.w*va.y; a3[2] += pa.w*va.z; a3[3] += pa.w*va.w;
            a0[0] += pb.x*vb.x; a0[1] += pb.x*vb.y; a0[2] += pb.x*vb.z; a0[3] += pb.x*vb.w;
            a1[0] += pb.y*vb.x; a1[1] += pb.y*vb.y; a1[2] += pb.y*vb.z; a1[3] += pb.y*vb.w;
            a2[0] += pb.z*vb.x; a2[1] += pb.z*vb.y; a2[2] += pb.z*vb.z; a2[3] += pb.z*vb.w;
            a3[0] += pb.w*vb.x; a3[1] += pb.w*vb.y; a3[2] += pb.w*vb.z; a3[3] += pb.w*vb.w;
        }
        if (last && w < 4) {                     // tail rows (already in values)
            int r = KV_ + w;
            float4 v = *(const float4*)(values + (bh * KVT + r) * HD_ + lane * 4);
            float4 p = *(const float4*)(sp + (CH2 + w) * 4);
            a0[0] += p.x*v.x; a0[1] += p.x*v.y; a0[2] += p.x*v.z; a0[3] += p.x*v.w;
            a1[0] += p.y*v.x; a1[1] += p.y*v.y; a1[2] += p.y*v.z; a1[3] += p.y*v.w;
            a2[0] += p.z*v.x; a2[1] += p.z*v.y; a2[2] += p.z*v.z; a2[3] += p.z*v.w;
            a3[0] += p.w*v.x; a3[1] += p.w*v.y; a3[2] += p.w*v.z; a3[3] += p.w*v.w;
        }
    }
    __syncthreads();                             // sp/ssc dead; reuse for partials

    // ---- cross-warp reduce -> per-chunk partial ----
    float* part = smem_all;                      // [8 warps][4 qi][128] = 4096 floats
    *(float4*)&part[(w*4 + 0)*128 + lane*4] = make_float4(a0[0], a0[1], a0[2], a0[3]);
    *(float4*)&part[(w*4 + 1)*128 + lane*4] = make_float4(a1[0], a1[1], a1[2], a1[3]);
    *(float4*)&part[(w*4 + 2)*128 + lane*4] = make_float4(a2[0], a2[1], a2[2], a2[3]);
    *(float4*)&part[(w*4 + 3)*128 + lane*4] = make_float4(a3[0], a3[1], a3[2], a3[3]);
    __syncthreads();
    for (int o = tid; o < 512; o += 256) {
        int qi = o >> 7, c = o & 127;
        float s = 0.f;
        #pragma unroll
        for (int w2 = 0; w2 < 8; w2++) s += part[(w2*4 + qi)*128 + c];
        g_pout[((bh*4 + qi) * NCHK + cy) * HD_ + c] = s;
    }
}

// ---------------------------------------------------------------------------
// Exact log-sum-exp combine of 8 chunk partials -> g_attnout
// ---------------------------------------------------------------------------
__global__ void __launch_bounds__(512) combine_k() {
    int bh = blockIdx.x;
    int t = threadIdx.x;
    int qi = t >> 7, hd = t & 127;
    int row = bh * 4 + qi;

    float ms[NCHK], ss[NCHK];
    float M = -3.0e38f;
    #pragma unroll
    for (int c = 0; c < NCHK; c++) {
        ms[c] = g_cm[row * NCHK + c];
        ss[c] = g_cs[row * NCHK + c];
        M = fmaxf(M, ms[c]);
    }
    float T = 0.f, o = 0.f;
    #pragma unroll
    for (int c = 0; c < NCHK; c++) {
        float wgt = expf(ms[c] - M);
        T += ss[c] * wgt;
        o += g_pout[(row * NCHK + c) * HD_ + hd] * wgt;
    }
    g_attnout[row * HD_ + hd] = o / T;
}

// ---------------------------------------------------------------------------
extern "C" void kernel_launch(void* const* d_in, const int* in_sizes, int n_in,
                              void* d_out, int out_size) {
    const float* x    = (const float*)d_in[0];
    const float* mask = (const float*)d_in[1];
    const float* kc   = (const float*)d_in[2];
    const float* vc   = (const float*)d_in[3];
    const float* qw   = (const float*)d_in[4];
    const float* kw   = (const float*)d_in[5];
    const float* vw   = (const float*)d_in[6];
    const float* ow   = (const float*)d_in[7];

    float* out    = (float*)d_out;
    float* keys   = out + OUT_ELEMS;
    float* values = keys + KEYS_ELEMS;

    init_kernel<<<1536, 256>>>(out);

    gemm_qkv<<<dim3(32, SPLITK, 3), 256>>>(x, qw, kw, vw);

    rope_scatter<<<dim3(256, 3), 256>>>(keys, values);

    attn_stream<<<dim3(BH, NCHK), 256>>>(kc, vc, mask, keys, values);

    combine_k<<<BH, 512>>>();

    gemm_o<<<dim3(32, 8), 256>>>(ow, out);
}

// round 15
// speedup vs baseline: 1.0474x; 1.0474x over previous
#include <cuda_runtime.h>
#include <math.h>
#include <mma.h>

using namespace nvcuda;

// Problem constants (fixed shapes)
#define B_    16
#define H_    16
#define BH    256          // B*H
#define L_    4
#define D_    2048
#define HD_   128
#define KV_   4096
#define KVT   4100         // KV + L
#define M_    64           // B*L rows
#define CH2   512          // kv chunk size (8 chunks cover KV exactly)
#define LDA   36           // padded smem ld (multiple of 4 floats = 16B)

// Output layout (concatenated): out[131072], keys[256*4100*128], values[...]
#define OUT_ELEMS   (M_*D_)                 // 131072
#define KEYS_ELEMS  (BH*KVT*HD_)            // 134348800

// Scratch
__device__ float g_qkv[3*M_*D_];            // raw q,k,v projections
__device__ float g_q[BH*L_*HD_];            // roped q, (b,h,l,hd)
__device__ float g_attnout[BH*L_*HD_];      // attention output accum (b,h,l,hd)
__device__ float g_scores[BH*L_*KVT];       // raw scores (pre-softmax)
__device__ float g_rowm[BH*L_];             // per-row max
__device__ float g_rowinv[BH*L_];           // per-row 1/sum(exp)
__device__ float g_rc[L_][64];
__device__ float g_rs[L_][64];

// ---------------------------------------------------------------------------
// init: zero accumulators + out region, build rope table (fp64 trig)
// ---------------------------------------------------------------------------
__global__ void __launch_bounds__(256) init_kernel(float* __restrict__ out) {
    int t = blockIdx.x * blockDim.x + threadIdx.x;
    if (t < 3*M_*D_) g_qkv[t] = 0.f;
    if (t < BH*L_*HD_) { g_attnout[t] = 0.f; out[t] = 0.f; }
    if (t < 256) {
        int l = t >> 6, i = t & 63;
        double inv = pow(10000.0, -(double)(2*i) / 128.0);
        float invf = (float)inv;                       // match jax f32 inv_freq
        float ang = (float)(KV_ + l) * invf;           // f32 angle like reference
        g_rc[l][i] = (float)cos((double)ang);
        g_rs[l][i] = (float)sin((double)ang);
    }
}

// ---------------------------------------------------------------------------
// WMMA tf32 3x-compensated tile compute shared by both GEMM kernels.
// CTA computes C[64 x 64] over a K-slice; warps own 16x32 strips.
// ---------------------------------------------------------------------------
__device__ __forceinline__ void tf32_split_a(
        wmma::fragment<wmma::matrix_a,16,16,8,wmma::precision::tf32,wmma::row_major>& hi,
        wmma::fragment<wmma::matrix_a,16,16,8,wmma::precision::tf32,wmma::row_major>& lo) {
    #pragma unroll
    for (int i = 0; i < hi.num_elements; i++) {
        float x = hi.x[i];
        float h = wmma::__float_to_tf32(x);
        lo.x[i] = wmma::__float_to_tf32(x - h);
        hi.x[i] = h;
    }
}
__device__ __forceinline__ void tf32_split_b(
        wmma::fragment<wmma::matrix_b,16,16,8,wmma::precision::tf32,wmma::col_major>& hi,
        wmma::fragment<wmma::matrix_b,16,16,8,wmma::precision::tf32,wmma::col_major>& lo) {
    #pragma unroll
    for (int i = 0; i < hi.num_elements; i++) {
        float x = hi.x[i];
        float h = wmma::__float_to_tf32(x);
        lo.x[i] = wmma::__float_to_tf32(x - h);
        hi.x[i] = h;
    }
}

// ---------------------------------------------------------------------------
// Fused QKV projection (WMMA tf32 3x): C[64x2048] += A[64x2048] * W^T
// blockIdx.z selects q/k/v; blockIdx.y is the split-K slice (atomic combine).
// ---------------------------------------------------------------------------
__global__ void __launch_bounds__(256) gemm_qkv(const float* __restrict__ A,
                         const float* __restrict__ qw,
                         const float* __restrict__ kw,
                         const float* __restrict__ vw) {
    __shared__ __align__(16) float smem[2 * 64 * LDA];   // As | Bs ; reused as Cs
    float* As = smem;
    float* Bs = smem + 64 * LDA;

    int mode = blockIdx.z;
    const float* __restrict__ W = (mode == 0) ? qw : ((mode == 1) ? kw : vw);
    float* __restrict__ C = g_qkv + mode * M_ * D_;

    int tid = threadIdx.x, w = tid >> 5;
    int n0 = blockIdx.x * 64;
    int KS = D_ / gridDim.y;
    int kbase = blockIdx.y * KS;

    int r0 = (w >> 1) * 16;      // warp row strip (0..48)
    int c0 = (w & 1) * 32;       // warp col strip (0 or 32)

    wmma::fragment<wmma::accumulator,16,16,8,float> acc0, acc1;
    wmma::fill_fragment(acc0, 0.f);
    wmma::fill_fragment(acc1, 0.f);

    for (int k0 = kbase; k0 < kbase + KS; k0 += 32) {
        #pragma unroll
        for (int rep = 0; rep < 2; rep++) {
            int fid = tid + rep * 256;
            int row = fid >> 3;
            int c4  = (fid & 7) * 4;
            int k   = k0 + c4;
            *(float4*)&As[row * LDA + c4] = *(const float4*)(A + row * D_ + k);
            *(float4*)&Bs[row * LDA + c4] = *(const float4*)(W + (n0 + row) * D_ + k);
        }
        __syncthreads();
        #pragma unroll
        for (int ks = 0; ks < 4; ks++) {
            wmma::fragment<wmma::matrix_a,16,16,8,wmma::precision::tf32,wmma::row_major> ah, al;
            wmma::load_matrix_sync(ah, &As[r0 * LDA + ks * 8], LDA);
            tf32_split_a(ah, al);
            wmma::fragment<wmma::matrix_b,16,16,8,wmma::precision::tf32,wmma::col_major> bh0, bl0, bh1, bl1;
            wmma::load_matrix_sync(bh0, &Bs[c0 * LDA + ks * 8], LDA);
            wmma::load_matrix_sync(bh1, &Bs[(c0 + 16) * LDA + ks * 8], LDA);
            tf32_split_b(bh0, bl0);
            tf32_split_b(bh1, bl1);
            wmma::mma_sync(acc0, ah, bh0, acc0);
            wmma::mma_sync(acc0, ah, bl0, acc0);
            wmma::mma_sync(acc0, al, bh0, acc0);
            wmma::mma_sync(acc1, ah, bh1, acc1);
            wmma::mma_sync(acc1, ah, bl1, acc1);
            wmma::mma_sync(acc1, al, bh1, acc1);
        }
        __syncthreads();
    }

    // epilogue: stage to smem (reuse), then atomic split-K combine
    float* Cs = smem;                 // 64*64 = 4096 floats < 2*64*LDA = 4608
    wmma::store_matrix_sync(&Cs[r0 * 64 + c0],      acc0, 64, wmma::mem_row_major);
    wmma::store_matrix_sync(&Cs[r0 * 64 + c0 + 16], acc1, 64, wmma::mem_row_major);
    __syncthreads();
    for (int i = tid; i < 4096; i += 256) {
        int row = i >> 6, col = i & 63;
        atomicAdd(&C[row * D_ + n0 + col], Cs[i]);
    }
}

// ---------------------------------------------------------------------------
// O projection (WMMA tf32 3x): out[64x2048] += attnout(gathered) * OW^T
// ---------------------------------------------------------------------------
__global__ void __launch_bounds__(256) gemm_o(const float* __restrict__ W,
                                              float* __restrict__ C) {
    __shared__ __align__(16) float smem[2 * 64 * LDA];
    float* As = smem;
    float* Bs = smem + 64 * LDA;
    const float* __restrict__ A = g_attnout;

    int tid = threadIdx.x, w = tid >> 5;
    int n0 = blockIdx.x * 64;
    int KS = D_ / gridDim.y;
    int kbase = blockIdx.y * KS;

    int r0 = (w >> 1) * 16;
    int c0 = (w & 1) * 32;

    wmma::fragment<wmma::accumulator,16,16,8,float> acc0, acc1;
    wmma::fill_fragment(acc0, 0.f);
    wmma::fill_fragment(acc1, 0.f);

    for (int k0 = kbase; k0 < kbase + KS; k0 += 32) {
        #pragma unroll
        for (int rep = 0; rep < 2; rep++) {
            int fid = tid + rep * 256;
            int row = fid >> 3;
            int c4  = (fid & 7) * 4;
            int k   = k0 + c4;
            // gather: A row m=(b,l), col k=(h,hd) from (b,h,l,hd) layout
            int b = row >> 2, l = row & 3, h = k >> 7, hd = k & 127;
            *(float4*)&As[row * LDA + c4] =
                *(const float4*)(A + (((b << 4) + h) * 4 + l) * HD_ + hd);
            *(float4*)&Bs[row * LDA + c4] = *(const float4*)(W + (n0 + row) * D_ + k);
        }
        __syncthreads();
        #pragma unroll
        for (int ks = 0; ks < 4; ks++) {
            wmma::fragment<wmma::matrix_a,16,16,8,wmma::precision::tf32,wmma::row_major> ah, al;
            wmma::load_matrix_sync(ah, &As[r0 * LDA + ks * 8], LDA);
            tf32_split_a(ah, al);
            wmma::fragment<wmma::matrix_b,16,16,8,wmma::precision::tf32,wmma::col_major> bh0, bl0, bh1, bl1;
            wmma::load_matrix_sync(bh0, &Bs[c0 * LDA + ks * 8], LDA);
            wmma::load_matrix_sync(bh1, &Bs[(c0 + 16) * LDA + ks * 8], LDA);
            tf32_split_b(bh0, bl0);
            tf32_split_b(bh1, bl1);
            wmma::mma_sync(acc0, ah, bh0, acc0);
            wmma::mma_sync(acc0, ah, bl0, acc0);
            wmma::mma_sync(acc0, al, bh0, acc0);
            wmma::mma_sync(acc1, ah, bh1, acc1);
            wmma::mma_sync(acc1, ah, bl1, acc1);
            wmma::mma_sync(acc1, al, bh1, acc1);
        }
        __syncthreads();
    }

    float* Cs = smem;
    wmma::store_matrix_sync(&Cs[r0 * 64 + c0],      acc0, 64, wmma::mem_row_major);
    wmma::store_matrix_sync(&Cs[r0 * 64 + c0 + 16], acc1, 64, wmma::mem_row_major);
    __syncthreads();
    for (int i = tid; i < 4096; i += 256) {
        int row = i >> 6, col = i & 63;
        atomicAdd(&C[row * D_ + n0 + col], Cs[i]);
    }
}

// ---------------------------------------------------------------------------
// rope + scatter: q -> g_q (roped), k -> keys tail (roped), v -> values tail
// ---------------------------------------------------------------------------
__global__ void __launch_bounds__(256) rope_scatter(float* __restrict__ keys,
                                                    float* __restrict__ values) {
    int mat = blockIdx.y;                       // 0=q, 1=k, 2=v
    int p = blockIdx.x * 256 + threadIdx.x;     // pair id, 0..65535
    int m  = p >> 10;                            // row 0..63
    int n0 = (p & 1023) * 2;                     // even column
    int b = m >> 2, l = m & 3;
    int h = n0 >> 7, hd = n0 & 127;
    const float* src = g_qkv + mat * M_ * D_ + m * D_ + n0;
    float x1 = src[0], x2 = src[1];
    int bh = (b << 4) + h;
    if (mat == 2) {
        float* dst = values + (bh * KVT + KV_ + l) * HD_ + hd;
        dst[0] = x1; dst[1] = x2;
    } else {
        int i = hd >> 1;
        float c = g_rc[l][i], s = g_rs[l][i];
        float r1 = x1 * c - x2 * s;
        float r2 = x1 * s + x2 * c;
        if (mat == 0) {
            float* dst = g_q + (bh * 4 + l) * HD_ + hd;
            dst[0] = r1; dst[1] = r2;
        } else {
            float* dst = keys + (bh * KVT + KV_ + l) * HD_ + hd;
            dst[0] = r1; dst[1] = r2;
        }
    }
}

// ---------------------------------------------------------------------------
// helpers for the streaming kernels (R10-proven configuration)
// ---------------------------------------------------------------------------
__device__ __forceinline__ void dot4(float4 kv, float4 q0, float4 q1,
                                     float4 q2, float4 q3,
                                     float& s0, float& s1, float& s2, float& s3) {
    s0 = kv.x*q0.x + kv.y*q0.y + kv.z*q0.z + kv.w*q0.w;
    s1 = kv.x*q1.x + kv.y*q1.y + kv.z*q1.z + kv.w*q1.w;
    s2 = kv.x*q2.x + kv.y*q2.y + kv.z*q2.z + kv.w*q2.w;
    s3 = kv.x*q3.x + kv.y*q3.y + kv.z*q3.z + kv.w*q3.w;
}

__device__ __forceinline__ void red4(float& s0, float& s1, float& s2, float& s3) {
    #pragma unroll
    for (int off = 16; off; off >>= 1) {
        s0 += __shfl_xor_sync(0xFFFFFFFFu, s0, off);
        s1 += __shfl_xor_sync(0xFFFFFFFFu, s1, off);
        s2 += __shfl_xor_sync(0xFFFFFFFFu, s2, off);
        s3 += __shfl_xor_sync(0xFFFFFFFFu, s3, off);
    }
}

// ---------------------------------------------------------------------------
// Fused K-cache copy + scores: warp per kv row, 2 rows in flight per warp.
// ---------------------------------------------------------------------------
__global__ void __launch_bounds__(256) kcopy_scores(
        const float* __restrict__ kc, const float* __restrict__ mask,
        float* __restrict__ keys) {
    int bh = blockIdx.x;
    int start = blockIdx.y * CH2;               // chunks cover [0,4096)
    bool last = (blockIdx.y == 7);
    int tid = threadIdx.x, w = tid >> 5, lane = tid & 31;
    __shared__ float ssc[4][CH2 + 4];

    const float* qb = g_q + bh * 4 * HD_ + lane * 4;
    float4 q0 = *(const float4*)(qb + 0 * HD_);
    float4 q1 = *(const float4*)(qb + 1 * HD_);
    float4 q2 = *(const float4*)(qb + 2 * HD_);
    float4 q3 = *(const float4*)(qb + 3 * HD_);

    const float* kin  = kc   + (bh * KV_ + start) * HD_ + lane * 4;
    float*       kout = keys + (bh * KVT + start) * HD_ + lane * 4;

    for (int rr = w; rr < CH2; rr += 16) {
        float4 ka = *(const float4*)(kin + rr * HD_);
        float4 kb = *(const float4*)(kin + (rr + 8) * HD_);
        *(float4*)(kout + rr * HD_)       = ka;
        *(float4*)(kout + (rr + 8) * HD_) = kb;
        float a0, a1, a2, a3, b0, b1, b2, b3;
        dot4(ka, q0, q1, q2, q3, a0, a1, a2, a3);
        dot4(kb, q0, q1, q2, q3, b0, b1, b2, b3);
        red4(a0, a1, a2, a3);
        red4(b0, b1, b2, b3);
        if (lane == 0) {
            ssc[0][rr] = a0; ssc[1][rr] = a1; ssc[2][rr] = a2; ssc[3][rr] = a3;
            ssc[0][rr+8] = b0; ssc[1][rr+8] = b1; ssc[2][rr+8] = b2; ssc[3][rr+8] = b3;
        }
    }

    if (last && w < 4) {                         // tail rows 4096..4099 (already in keys)
        int r = KV_ + w;
        float4 kv = *(const float4*)(keys + (bh * KVT + r) * HD_ + lane * 4);
        float t0, t1, t2, t3;
        dot4(kv, q0, q1, q2, q3, t0, t1, t2, t3);
        red4(t0, t1, t2, t3);
        if (lane == 0) {
            ssc[0][CH2 + w] = t0; ssc[1][CH2 + w] = t1;
            ssc[2][CH2 + w] = t2; ssc[3][CH2 + w] = t3;
        }
    }
    __syncthreads();

    const float scale = 0.08838834764831845f;   // 128^-0.5
    int len = last ? (CH2 + 4) : CH2;
    #pragma unroll
    for (int qi = 0; qi < 4; qi++)
        for (int i = tid; i < len; i += 256)
            g_scores[(bh * 4 + qi) * KVT + start + i] =
                ssc[qi][i] * scale + mask[qi * KVT + start + i];
}

// ---------------------------------------------------------------------------
// Row stats: per-row max and 1/sum(exp) over 4100 elems (register-resident)
// ---------------------------------------------------------------------------
__global__ void __launch_bounds__(256) rowstat_k() {
    int row = blockIdx.x;                  // bh*4+qi, 0..1023
    const float* s = g_scores + row * KVT;
    int tid = threadIdx.x, lane = tid & 31, w = tid >> 5;
    __shared__ float red[8];

    float v[17];
    float mx = -3.0e38f;
    #pragma unroll
    for (int i = 0; i < 17; i++) {
        int idx = tid + i * 256;
        v[i] = (idx < KVT) ? s[idx] : -3.0e38f;
        mx = fmaxf(mx, v[i]);
    }
    #pragma unroll
    for (int off = 16; off; off >>= 1) mx = fmaxf(mx, __shfl_xor_sync(0xFFFFFFFFu, mx, off));
    if (lane == 0) red[w] = mx;
    __syncthreads();
    float bm = red[0];
    #pragma unroll
    for (int j = 1; j < 8; j++) bm = fmaxf(bm, red[j]);

    float sum = 0.f;
    #pragma unroll
    for (int i = 0; i < 17; i++) sum += expf(v[i] - bm);
    #pragma unroll
    for (int off = 16; off; off >>= 1) sum += __shfl_xor_sync(0xFFFFFFFFu, sum, off);
    __syncthreads();
    if (lane == 0) red[w] = sum;
    __syncthreads();
    if (tid == 0) {
        float tot = 0.f;
        #pragma unroll
        for (int j = 0; j < 8; j++) tot += red[j];
        g_rowm[row] = bm;
        g_rowinv[row] = 1.0f / tot;
    }
}

// ---------------------------------------------------------------------------
// Fused V-cache copy + attn @ V accumulation (R10-proven configuration)
// ---------------------------------------------------------------------------
__global__ void __launch_bounds__(256) vcopy_out(const float* __restrict__ vc,
                                                 float* __restrict__ values) {
    int bh = blockIdx.x;
    int start = blockIdx.y * CH2;
    bool last = (blockIdx.y == 7);
    int tid = threadIdx.x, w = tid >> 5, lane = tid & 31;
    __shared__ __align__(16) float sp[(CH2 + 4) * 4];   // [row_local][qi]

    int len = last ? (CH2 + 4) : CH2;
    #pragma unroll
    for (int qi = 0; qi < 4; qi++) {
        float m   = g_rowm[bh * 4 + qi];
        float inv = g_rowinv[bh * 4 + qi];
        for (int i = tid; i < len; i += 256)
            sp[i * 4 + qi] = expf(g_scores[(bh * 4 + qi) * KVT + start + i] - m) * inv;
    }
    __syncthreads();

    const float* vin  = vc     + (bh * KV_ + start) * HD_ + lane * 4;
    float*       vout = values + (bh * KVT + start) * HD_ + lane * 4;

    float a0[4] = {}, a1[4] = {}, a2[4] = {}, a3[4] = {};
    for (int rr = w; rr < CH2; rr += 16) {
        float4 va = *(const float4*)(vin + rr * HD_);
        float4 vb = *(const float4*)(vin + (rr + 8) * HD_);
        *(float4*)(vout + rr * HD_)       = va;
        *(float4*)(vout + (rr + 8) * HD_) = vb;
        float4 pa = *(const float4*)(sp + rr * 4);
        float4 pb = *(const float4*)(sp + (rr + 8) * 4);
        a0[0] += pa.x*va.x; a0[1] += pa.x*va.y; a0[2] += pa.x*va.z; a0[3] += pa.x*va.w;
        a1[0] += pa.y*va.x; a1[1] += pa.y*va.y; a1[2] += pa.y*va.z; a1[3] += pa.y*va.w;
        a2[0] += pa.z*va.x; a2[1] += pa.z*va.y; a2[2] += pa.z*va.z; a2[3] += pa.z*va.w;
        a3[0] += pa.w*va.x; a3[1] += pa.w*va.y; a3[2] += pa.w*va.z; a3[3] += pa.w*va.w;
        a0[0] += pb.x*vb.x; a0[1] += pb.x*vb.y; a0[2] += pb.x*vb.z; a0[3] += pb.x*vb.w;
        a1[0] += pb.y*vb.x; a1[1] += pb.y*vb.y; a1[2] += pb.y*vb.z; a1[3] += pb.y*vb.w;
        a2[0] += pb.z*vb.x; a2[1] += pb.z*vb.y; a2[2] += pb.z*vb.z; a2[3] += pb.z*vb.w;
        a3[0] += pb.w*vb.x; a3[1] += pb.w*vb.y; a3[2] += pb.w*vb.z; a3[3] += pb.w*vb.w;
    }

    if (last && w < 4) {                         // tail rows (already in values)
        int r = KV_ + w;
        float4 v = *(const float4*)(values + (bh * KVT + r) * HD_ + lane * 4);
        float4 p = *(const float4*)(sp + (CH2 + w) * 4);
        a0[0] += p.x*v.x; a0[1] += p.x*v.y; a0[2] += p.x*v.z; a0[3] += p.x*v.w;
        a1[0] += p.y*v.x; a1[1] += p.y*v.y; a1[2] += p.y*v.z; a1[3] += p.y*v.w;
        a2[0] += p.z*v.x; a2[1] += p.z*v.y; a2[2] += p.z*v.z; a2[3] += p.z*v.w;
        a3[0] += p.w*v.x; a3[1] += p.w*v.y; a3[2] += p.w*v.z; a3[3] += p.w*v.w;
    }

    float* ao = g_attnout + bh * 4 * HD_ + lane * 4;
    #pragma unroll
    for (int e = 0; e < 4; e++) {
        atomicAdd(&ao[0 * HD_ + e], a0[e]);
        atomicAdd(&ao[1 * HD_ + e], a1[e]);
        atomicAdd(&ao[2 * HD_ + e], a2[e]);
        atomicAdd(&ao[3 * HD_ + e], a3[e]);
    }
}

// ---------------------------------------------------------------------------
extern "C" void kernel_launch(void* const* d_in, const int* in_sizes, int n_in,
                              void* d_out, int out_size) {
    const float* x    = (const float*)d_in[0];
    const float* mask = (const float*)d_in[1];
    const float* kc   = (const float*)d_in[2];
    const float* vc   = (const float*)d_in[3];
    const float* qw   = (const float*)d_in[4];
    const float* kw   = (const float*)d_in[5];
    const float* vw   = (const float*)d_in[6];
    const float* ow   = (const float*)d_in[7];

    float* out    = (float*)d_out;
    float* keys   = out + OUT_ELEMS;
    float* values = keys + KEYS_ELEMS;

    init_kernel<<<1536, 256>>>(out);

    gemm_qkv<<<dim3(32, 4, 3), 256>>>(x, qw, kw, vw);

    rope_scatter<<<dim3(256, 3), 256>>>(keys, values);

    kcopy_scores<<<dim3(BH, 8), 256>>>(kc, mask, keys);
    rowstat_k<<<BH * L_, 256>>>();
    vcopy_out<<<dim3(BH, 8), 256>>>(vc, values);

    gemm_o<<<dim3(32, 8), 256>>>(ow, out);
}